// round 5
// baseline (speedup 1.0000x reference)
#include <cuda_runtime.h>

#define N_ROWS (64 * 1024)
#define T_LEN  1200
#define WPB    8                        // warps per block (R3-proven config)
#define NBLOCKS (N_ROWS / WPB)          // 8192

// Scratch (allowed: __device__ globals, no allocation)
__device__ float        g_feat[N_ROWS];
__device__ unsigned int g_count = 0;    // last-block election; reset each run

// ---------------------------------------------------------------------------
// Fused kernel: per-row temporal pipeline (one warp per row) identical to the
// 54.4us R3 version, then the LAST block runs classifier + softmax.
// Lengths: 1200 -> 600 -> 200 -> 100 -> 50 -> 25 -> 12 -> 6 -> 3 -> 1
// ---------------------------------------------------------------------------
__global__ __launch_bounds__(WPB * 32)
void fused_kernel(
    const float* __restrict__ x,
    const float* __restrict__ c0_w, const float* __restrict__ c0_b,
    const float* __restrict__ c2_w, const float* __restrict__ c2_b,
    const float* __restrict__ c4_w, const float* __restrict__ c4_b,
    const float* __restrict__ c6_w, const float* __restrict__ c6_b,
    const float* __restrict__ c8_w, const float* __restrict__ c8_b,
    const float* __restrict__ cls_w, const float* __restrict__ cls_b,
    float* __restrict__ out)
{
    __shared__ float sA[WPB][200];
    __shared__ float sB[WPB][100];
    __shared__ bool  s_last;

    const int warp = threadIdx.x >> 5;
    const int lane = threadIdx.x & 31;
    const int row  = blockIdx.x * WPB + warp;   // grid exactly covers N_ROWS

    const float* __restrict__ xr = x + (size_t)row * T_LEN;

    // --- Stage 0+1: conv(k=2,s=2) + maxpool3 + relu : 1200 -> 200 ----------
    // (R3 layout: lane j -> conv outputs 3j..3j+2 from x[6j..6j+5], float2)
    const float w00 = c0_w[0], w01 = c0_w[1], b0 = c0_b[0];
    float* h2 = sA[warp];
    #pragma unroll
    for (int it = 0; it < 7; ++it) {
        int j = lane + 32 * it;            // 7*32 = 224 >= 200
        if (j < 200) {
            const float2* p = reinterpret_cast<const float2*>(xr + 6 * j);
            float2 a = p[0], b = p[1], c = p[2];
            float m0 = w00 * a.x + w01 * a.y;
            float m1 = w00 * b.x + w01 * b.y;
            float m2 = w00 * c.x + w01 * c.y;
            float m  = fmaxf(m0, fmaxf(m1, m2));
            h2[j] = fmaxf(m + b0, 0.0f);
        }
    }
    __syncwarp();

    // --- Stage 2: conv(k=4,s=2,p=1) : 200 -> 100 ---------------------------
    const float w20 = c2_w[0], w21 = c2_w[1], w22 = c2_w[2], w23 = c2_w[3], b2 = c2_b[0];
    float* y3 = sB[warp];
    #pragma unroll
    for (int it = 0; it < 4; ++it) {
        int i = lane + 32 * it;
        if (i < 100) {
            float v0 = (i == 0)          ? 0.0f : h2[2 * i - 1];
            float v1 = h2[2 * i];
            float v2 = h2[2 * i + 1];
            float v3 = (2 * i + 2 < 200) ? h2[2 * i + 2] : 0.0f;
            y3[i] = b2 + w20 * v0 + w21 * v1 + w22 * v2 + w23 * v3;
        }
    }
    __syncwarp();

    // --- Stage 3: maxpool2 + relu : 100 -> 50 -------------------------------
    float* h4 = sA[warp];
    #pragma unroll
    for (int it = 0; it < 2; ++it) {
        int i = lane + 32 * it;
        if (i < 50)
            h4[i] = fmaxf(fmaxf(y3[2 * i], y3[2 * i + 1]), 0.0f);
    }
    __syncwarp();

    // --- Stage 4: conv(k=4,s=2,p=1) : 50 -> 25 ------------------------------
    const float w40 = c4_w[0], w41 = c4_w[1], w42 = c4_w[2], w43 = c4_w[3], b4 = c4_b[0];
    float* y5 = sB[warp];
    if (lane < 25) {
        int i = lane;
        float v0 = (i == 0)         ? 0.0f : h4[2 * i - 1];
        float v1 = h4[2 * i];
        float v2 = h4[2 * i + 1];
        float v3 = (2 * i + 2 < 50) ? h4[2 * i + 2] : 0.0f;
        y5[i] = b4 + w40 * v0 + w41 * v1 + w42 * v2 + w43 * v3;
    }
    __syncwarp();

    // --- Stage 5: maxpool2 + relu : 25 -> 12 --------------------------------
    float* h6 = sA[warp];
    if (lane < 12)
        h6[lane] = fmaxf(fmaxf(y5[2 * lane], y5[2 * lane + 1]), 0.0f);
    __syncwarp();

    // --- Stage 6: conv(k=4,s=2,p=1) : 12 -> 6 -------------------------------
    const float w60 = c6_w[0], w61 = c6_w[1], w62 = c6_w[2], w63 = c6_w[3], b6 = c6_b[0];
    float* y7 = sB[warp];
    if (lane < 6) {
        int i = lane;
        float v0 = (i == 0)         ? 0.0f : h6[2 * i - 1];
        float v1 = h6[2 * i];
        float v2 = h6[2 * i + 1];
        float v3 = (2 * i + 2 < 12) ? h6[2 * i + 2] : 0.0f;
        y7[i] = b6 + w60 * v0 + w61 * v1 + w62 * v2 + w63 * v3;
    }
    __syncwarp();

    // --- Stage 7: maxpool2 + relu : 6 -> 3 ----------------------------------
    float* h8 = sA[warp];
    if (lane < 3)
        h8[lane] = fmaxf(fmaxf(y7[2 * lane], y7[2 * lane + 1]), 0.0f);
    __syncwarp();

    // --- Stage 8: conv(k=3,s=1,p=0) : 3 -> 1 --------------------------------
    if (lane == 0)
        g_feat[row] = c8_b[0] + c8_w[0] * h8[0] + c8_w[1] * h8[1] + c8_w[2] * h8[2];

    // ========================================================================
    // Last-block election. Cheap variant: bar.sync orders all warps' g_feat
    // stores at block scope; thread 0's fence.gpu is cumulative over them, so
    // ONE membar per block suffices (not one per thread).
    // ========================================================================
    __syncthreads();
    if (threadIdx.x == 0) {
        __threadfence();                               // release g_feat stores
        unsigned int prev = atomicAdd(&g_count, 1u);   // signal
        s_last = (prev == (unsigned int)(NBLOCKS - 1));
    }
    __syncthreads();
    if (!s_last) return;

    __threadfence();   // acquire: all blocks' g_feat stores now visible

    // --- Classifier: logits[b][c] = feat[b,:].cls_w[c,:] + cls_b[c] --------
    // 8 warps x 8 batches each; cls_w (12KB) via read-only cache, feat via L2.
    #pragma unroll
    for (int rep = 0; rep < 8; ++rep) {
        int b = warp + WPB * rep;
        const float* __restrict__ f = g_feat + b * 1024;
        float a0 = 0.f, a1 = 0.f, a2 = 0.f;
        #pragma unroll 8
        for (int k = 0; k < 32; ++k) {
            int n = k * 32 + lane;
            float v = __ldcg(f + n);
            a0 += v * __ldg(cls_w + n);
            a1 += v * __ldg(cls_w + 1024 + n);
            a2 += v * __ldg(cls_w + 2048 + n);
        }
        #pragma unroll
        for (int off = 16; off > 0; off >>= 1) {
            a0 += __shfl_down_sync(0xffffffffu, a0, off);
            a1 += __shfl_down_sync(0xffffffffu, a1, off);
            a2 += __shfl_down_sync(0xffffffffu, a2, off);
        }
        if (lane == 0) {
            float l0 = a0 + cls_b[0];
            float l1 = a1 + cls_b[1];
            float l2 = a2 + cls_b[2];
            float m  = fmaxf(l0, fmaxf(l1, l2));
            float e0 = expf(l0 - m), e1 = expf(l1 - m), e2 = expf(l2 - m);
            float inv = 1.0f / (e0 + e1 + e2);
            out[b * 3 + 0] = e0 * inv;
            out[b * 3 + 1] = e1 * inv;
            out[b * 3 + 2] = e2 * inv;
        }
    }

    // Reset counter for the next graph replay (deterministic across calls).
    __syncthreads();
    if (threadIdx.x == 0)
        g_count = 0;
}

// ---------------------------------------------------------------------------
// Input order per metadata:
// 0:x 1:c0_w 2:c0_b 3:c2_w 4:c2_b 5:c4_w 6:c4_b 7:c6_w 8:c6_b 9:c8_w 10:c8_b
// 11..14: gcn weights (dead code, unused) 15:cls_w 16:cls_b
// ---------------------------------------------------------------------------
extern "C" void kernel_launch(void* const* d_in, const int* in_sizes, int n_in,
                              void* d_out, int out_size)
{
    const float* x     = (const float*)d_in[0];
    const float* c0_w  = (const float*)d_in[1];
    const float* c0_b  = (const float*)d_in[2];
    const float* c2_w  = (const float*)d_in[3];
    const float* c2_b  = (const float*)d_in[4];
    const float* c4_w  = (const float*)d_in[5];
    const float* c4_b  = (const float*)d_in[6];
    const float* c6_w  = (const float*)d_in[7];
    const float* c6_b  = (const float*)d_in[8];
    const float* c8_w  = (const float*)d_in[9];
    const float* c8_b  = (const float*)d_in[10];
    const float* cls_w = (const float*)d_in[15];
    const float* cls_b = (const float*)d_in[16];
    float* out = (float*)d_out;

    fused_kernel<<<NBLOCKS, WPB * 32>>>(
        x, c0_w, c0_b, c2_w, c2_b, c4_w, c4_b, c6_w, c6_b, c8_w, c8_b,
        cls_w, cls_b, out);
}

// round 6
// speedup vs baseline: 2.0155x; 2.0155x over previous
#include <cuda_runtime.h>

#define N_ROWS (64 * 1024)
#define T_LEN  1200
#define WPB    8                        // warps per block (R3-proven config)
#define NBLOCKS (N_ROWS / WPB)          // 8192
#define BLOCKS_PER_BATCH 128            // 1024 nodes / 8 rows-per-block

// Scratch (allowed: __device__ globals, no allocation)
__device__ float        g_feat[N_ROWS];
// Per-batch completion counters, 256B apart (distinct LTS slices, no
// same-address ATOMG serialization, no bit-7 hash pair-collisions).
__device__ unsigned int g_cnt[64 * 64];

// ---------------------------------------------------------------------------
// Fused kernel: per-row temporal pipeline (one warp per row; identical to the
// 54.4us R3 body). The LAST block of each batch (128 blocks/batch) computes
// that batch's classifier logits + softmax. 64 independent elections.
// Lengths: 1200 -> 600 -> 200 -> 100 -> 50 -> 25 -> 12 -> 6 -> 3 -> 1
// ---------------------------------------------------------------------------
__global__ __launch_bounds__(WPB * 32)
void fused_kernel(
    const float* __restrict__ x,
    const float* __restrict__ c0_w, const float* __restrict__ c0_b,
    const float* __restrict__ c2_w, const float* __restrict__ c2_b,
    const float* __restrict__ c4_w, const float* __restrict__ c4_b,
    const float* __restrict__ c6_w, const float* __restrict__ c6_b,
    const float* __restrict__ c8_w, const float* __restrict__ c8_b,
    const float* __restrict__ cls_w, const float* __restrict__ cls_b,
    float* __restrict__ out)
{
    __shared__ float sA[WPB][200];
    __shared__ float sB[WPB][100];
    __shared__ float s_red[3][WPB];
    __shared__ bool  s_last;

    const int warp = threadIdx.x >> 5;
    const int lane = threadIdx.x & 31;
    const int row  = blockIdx.x * WPB + warp;   // grid exactly covers N_ROWS

    const float* __restrict__ xr = x + (size_t)row * T_LEN;

    // --- Stage 0+1: conv(k=2,s=2) + maxpool3 + relu : 1200 -> 200 ----------
    const float w00 = c0_w[0], w01 = c0_w[1], b0 = c0_b[0];
    float* h2 = sA[warp];
    #pragma unroll
    for (int it = 0; it < 7; ++it) {
        int j = lane + 32 * it;            // 7*32 = 224 >= 200
        if (j < 200) {
            const float2* p = reinterpret_cast<const float2*>(xr + 6 * j);
            float2 a = p[0], b = p[1], c = p[2];
            float m0 = w00 * a.x + w01 * a.y;
            float m1 = w00 * b.x + w01 * b.y;
            float m2 = w00 * c.x + w01 * c.y;
            float m  = fmaxf(m0, fmaxf(m1, m2));
            h2[j] = fmaxf(m + b0, 0.0f);
        }
    }
    __syncwarp();

    // --- Stage 2: conv(k=4,s=2,p=1) : 200 -> 100 ---------------------------
    const float w20 = c2_w[0], w21 = c2_w[1], w22 = c2_w[2], w23 = c2_w[3], b2 = c2_b[0];
    float* y3 = sB[warp];
    #pragma unroll
    for (int it = 0; it < 4; ++it) {
        int i = lane + 32 * it;
        if (i < 100) {
            float v0 = (i == 0)          ? 0.0f : h2[2 * i - 1];
            float v1 = h2[2 * i];
            float v2 = h2[2 * i + 1];
            float v3 = (2 * i + 2 < 200) ? h2[2 * i + 2] : 0.0f;
            y3[i] = b2 + w20 * v0 + w21 * v1 + w22 * v2 + w23 * v3;
        }
    }
    __syncwarp();

    // --- Stage 3: maxpool2 + relu : 100 -> 50 -------------------------------
    float* h4 = sA[warp];
    #pragma unroll
    for (int it = 0; it < 2; ++it) {
        int i = lane + 32 * it;
        if (i < 50)
            h4[i] = fmaxf(fmaxf(y3[2 * i], y3[2 * i + 1]), 0.0f);
    }
    __syncwarp();

    // --- Stage 4: conv(k=4,s=2,p=1) : 50 -> 25 ------------------------------
    const float w40 = c4_w[0], w41 = c4_w[1], w42 = c4_w[2], w43 = c4_w[3], b4 = c4_b[0];
    float* y5 = sB[warp];
    if (lane < 25) {
        int i = lane;
        float v0 = (i == 0)         ? 0.0f : h4[2 * i - 1];
        float v1 = h4[2 * i];
        float v2 = h4[2 * i + 1];
        float v3 = (2 * i + 2 < 50) ? h4[2 * i + 2] : 0.0f;
        y5[i] = b4 + w40 * v0 + w41 * v1 + w42 * v2 + w43 * v3;
    }
    __syncwarp();

    // --- Stage 5: maxpool2 + relu : 25 -> 12 --------------------------------
    float* h6 = sA[warp];
    if (lane < 12)
        h6[lane] = fmaxf(fmaxf(y5[2 * lane], y5[2 * lane + 1]), 0.0f);
    __syncwarp();

    // --- Stage 6: conv(k=4,s=2,p=1) : 12 -> 6 -------------------------------
    const float w60 = c6_w[0], w61 = c6_w[1], w62 = c6_w[2], w63 = c6_w[3], b6 = c6_b[0];
    float* y7 = sB[warp];
    if (lane < 6) {
        int i = lane;
        float v0 = (i == 0)         ? 0.0f : h6[2 * i - 1];
        float v1 = h6[2 * i];
        float v2 = h6[2 * i + 1];
        float v3 = (2 * i + 2 < 12) ? h6[2 * i + 2] : 0.0f;
        y7[i] = b6 + w60 * v0 + w61 * v1 + w62 * v2 + w63 * v3;
    }
    __syncwarp();

    // --- Stage 7: maxpool2 + relu : 6 -> 3 ----------------------------------
    float* h8 = sA[warp];
    if (lane < 3)
        h8[lane] = fmaxf(fmaxf(y7[2 * lane], y7[2 * lane + 1]), 0.0f);
    __syncwarp();

    // --- Stage 8: conv(k=3,s=1,p=0) : 3 -> 1 --------------------------------
    if (lane == 0)
        g_feat[row] = c8_b[0] + c8_w[0] * h8[0] + c8_w[1] * h8[1] + c8_w[2] * h8[2];

    // ========================================================================
    // Per-batch last-block election. 128 blocks per batch, 64 distinct
    // counter addresses (256B apart) -> no cross-batch atomic serialization.
    // ========================================================================
    const int b = blockIdx.x >> 7;               // batch id (128 blocks each)
    __syncthreads();                             // order all warps' g_feat STG
    if (threadIdx.x == 0) {
        __threadfence();                         // release this block's stores
        unsigned int prev = atomicAdd(&g_cnt[b * 64], 1u);
        s_last = (prev == (unsigned int)(BLOCKS_PER_BATCH - 1));
    }
    __syncthreads();
    if (!s_last) return;

    __threadfence();     // acquire: sibling blocks' g_feat stores visible

    // --- Classifier for batch b: logits[c] = feat[b,:].cls_w[c,:] + cls_b[c]
    // 256 threads, 4 elements each; feat is L2-hot (just written).
    {
        const float* __restrict__ f = g_feat + b * 1024;
        float a0 = 0.f, a1 = 0.f, a2 = 0.f;
        #pragma unroll
        for (int k = 0; k < 4; ++k) {
            int n = k * 256 + threadIdx.x;
            float v = __ldcg(f + n);
            a0 += v * __ldg(cls_w + n);
            a1 += v * __ldg(cls_w + 1024 + n);
            a2 += v * __ldg(cls_w + 2048 + n);
        }
        #pragma unroll
        for (int off = 16; off > 0; off >>= 1) {
            a0 += __shfl_down_sync(0xffffffffu, a0, off);
            a1 += __shfl_down_sync(0xffffffffu, a1, off);
            a2 += __shfl_down_sync(0xffffffffu, a2, off);
        }
        if (lane == 0) {
            s_red[0][warp] = a0;
            s_red[1][warp] = a1;
            s_red[2][warp] = a2;
        }
        __syncthreads();
        if (threadIdx.x == 0) {
            float l0 = cls_b[0], l1 = cls_b[1], l2 = cls_b[2];
            #pragma unroll
            for (int w = 0; w < WPB; ++w) {
                l0 += s_red[0][w];
                l1 += s_red[1][w];
                l2 += s_red[2][w];
            }
            float m  = fmaxf(l0, fmaxf(l1, l2));
            float e0 = expf(l0 - m), e1 = expf(l1 - m), e2 = expf(l2 - m);
            float inv = 1.0f / (e0 + e1 + e2);
            out[b * 3 + 0] = e0 * inv;
            out[b * 3 + 1] = e1 * inv;
            out[b * 3 + 2] = e2 * inv;
            g_cnt[b * 64] = 0;   // reset own counter for next graph replay
        }
    }
}

// ---------------------------------------------------------------------------
// Input order per metadata:
// 0:x 1:c0_w 2:c0_b 3:c2_w 4:c2_b 5:c4_w 6:c4_b 7:c6_w 8:c6_b 9:c8_w 10:c8_b
// 11..14: gcn weights (dead code, unused) 15:cls_w 16:cls_b
// ---------------------------------------------------------------------------
extern "C" void kernel_launch(void* const* d_in, const int* in_sizes, int n_in,
                              void* d_out, int out_size)
{
    const float* x     = (const float*)d_in[0];
    const float* c0_w  = (const float*)d_in[1];
    const float* c0_b  = (const float*)d_in[2];
    const float* c2_w  = (const float*)d_in[3];
    const float* c2_b  = (const float*)d_in[4];
    const float* c4_w  = (const float*)d_in[5];
    const float* c4_b  = (const float*)d_in[6];
    const float* c6_w  = (const float*)d_in[7];
    const float* c6_b  = (const float*)d_in[8];
    const float* c8_w  = (const float*)d_in[9];
    const float* c8_b  = (const float*)d_in[10];
    const float* cls_w = (const float*)d_in[15];
    const float* cls_b = (const float*)d_in[16];
    float* out = (float*)d_out;

    fused_kernel<<<NBLOCKS, WPB * 32>>>(
        x, c0_w, c0_b, c2_w, c2_b, c4_w, c4_b, c6_w, c6_b, c8_w, c8_b,
        cls_w, cls_b, out);
}